// round 1
// baseline (speedup 1.0000x reference)
#include <cuda_runtime.h>
#include <math.h>

// Flash attention, causal, fp32 SIMT baseline.
// B=2, H=16, S=2048, D=128. mask input ignored (analytic causal mask).

#define BM 64
#define BN 64
#define DH 128
#define NTHREADS 256
#define KV_STRIDE 132   // floats per row for sQ/sK/sV (33 float4, 2-way conflict worst case)
#define P_STRIDE 68     // floats per row for sP (conflict-free STS given 4-row lane groups)
#define LOG2E 1.4426950408889634f

static constexpr int S_SEQ = 2048;

__global__ __launch_bounds__(NTHREADS, 1)
void fa_fp32_kernel(const float* __restrict__ Q,
                    const float* __restrict__ K,
                    const float* __restrict__ V,
                    float* __restrict__ O)
{
    extern __shared__ float smem[];
    float* sQ = smem;                        // BM * KV_STRIDE
    float* sK = sQ + BM * KV_STRIDE;         // BN * KV_STRIDE
    float* sV = sK + BN * KV_STRIDE;         // BN * KV_STRIDE
    float* sP = sV + BN * KV_STRIDE;         // BM * P_STRIDE

    const int tid = threadIdx.x;
    const int tx  = tid & 15;    // 16 column groups
    const int ty  = tid >> 4;    // 16 row groups

    // heavy (late) q-tiles first for better causal load balance
    const int q_tile = gridDim.x - 1 - blockIdx.x;
    const int bh     = blockIdx.y;
    const int q0     = q_tile * BM;

    const float* Qb = Q + (size_t)bh * S_SEQ * DH;
    const float* Kb = K + (size_t)bh * S_SEQ * DH;
    const float* Vb = V + (size_t)bh * S_SEQ * DH;
    float*       Ob = O + (size_t)bh * S_SEQ * DH;

    // ---- load Q tile (64 x 128) coalesced, float4 ----
    #pragma unroll
    for (int k = 0; k < 8; k++) {
        int idx = tid + k * NTHREADS;      // 0..2047 float4 slots
        int r   = idx >> 5;                // row 0..63
        int d4  = idx & 31;                // float4 col 0..31
        float4 v = reinterpret_cast<const float4*>(Qb + (size_t)(q0 + r) * DH)[d4];
        reinterpret_cast<float4*>(sQ + r * KV_STRIDE)[d4] = v;
    }

    // per-thread state: 4 rows (ty*4+r), 8 output cols (tx*8..tx*8+7)
    float m_run[4], l_run[4], o_acc[4][8];
    #pragma unroll
    for (int r = 0; r < 4; r++) {
        m_run[r] = -1e30f;
        l_run[r] = 0.0f;
        #pragma unroll
        for (int d = 0; d < 8; d++) o_acc[r][d] = 0.0f;
    }

    const float sm_scale = 0.0883883476483184405f;  // 1/sqrt(128)
    const int ktiles = q_tile + 1;

    for (int kt = 0; kt < ktiles; kt++) {
        __syncthreads();  // previous iteration's sV/sP reads complete

        // ---- load K,V tiles ----
        const int k0 = kt * BN;
        #pragma unroll
        for (int k = 0; k < 8; k++) {
            int idx = tid + k * NTHREADS;
            int r   = idx >> 5;
            int d4  = idx & 31;
            reinterpret_cast<float4*>(sK + r * KV_STRIDE)[d4] =
                reinterpret_cast<const float4*>(Kb + (size_t)(k0 + r) * DH)[d4];
            reinterpret_cast<float4*>(sV + r * KV_STRIDE)[d4] =
                reinterpret_cast<const float4*>(Vb + (size_t)(k0 + r) * DH)[d4];
        }
        __syncthreads();

        // ---- scores: acc[r][c] = Q[ty*4+r] . K[c*16+tx] ----
        float acc[4][4];
        #pragma unroll
        for (int r = 0; r < 4; r++)
            #pragma unroll
            for (int c = 0; c < 4; c++) acc[r][c] = 0.0f;

        const float4* sQ4 = reinterpret_cast<const float4*>(sQ);
        const float4* sK4 = reinterpret_cast<const float4*>(sK);

        #pragma unroll 8
        for (int d4 = 0; d4 < 32; d4++) {
            float4 qv[4], kv[4];
            #pragma unroll
            for (int r = 0; r < 4; r++)
                qv[r] = sQ4[(ty * 4 + r) * 33 + d4];
            #pragma unroll
            for (int c = 0; c < 4; c++)
                kv[c] = sK4[(c * 16 + tx) * 33 + d4];
            #pragma unroll
            for (int r = 0; r < 4; r++)
                #pragma unroll
                for (int c = 0; c < 4; c++) {
                    acc[r][c] += qv[r].x * kv[c].x;
                    acc[r][c] += qv[r].y * kv[c].y;
                    acc[r][c] += qv[r].z * kv[c].z;
                    acc[r][c] += qv[r].w * kv[c].w;
                }
        }

        // ---- scale + causal mask (only diagonal tile needs masking) ----
        const bool diag = (kt == q_tile);
        #pragma unroll
        for (int r = 0; r < 4; r++) {
            #pragma unroll
            for (int c = 0; c < 4; c++) {
                float s = acc[r][c] * sm_scale;
                if (diag && (c * 16 + tx) > (ty * 4 + r)) s = -1e30f;
                acc[r][c] = s;
            }
        }

        // ---- online softmax per row + write P ----
        #pragma unroll
        for (int r = 0; r < 4; r++) {
            float mt = fmaxf(fmaxf(acc[r][0], acc[r][1]), fmaxf(acc[r][2], acc[r][3]));
            #pragma unroll
            for (int off = 8; off > 0; off >>= 1)
                mt = fmaxf(mt, __shfl_xor_sync(0xffffffffu, mt, off));

            float mnew = fmaxf(m_run[r], mt);
            float corr = exp2f((m_run[r] - mnew) * LOG2E);
            m_run[r] = mnew;

            float lsum = 0.0f;
            #pragma unroll
            for (int c = 0; c < 4; c++) {
                float p = exp2f((acc[r][c] - mnew) * LOG2E);
                acc[r][c] = p;
                lsum += p;
            }
            #pragma unroll
            for (int off = 8; off > 0; off >>= 1)
                lsum += __shfl_xor_sync(0xffffffffu, lsum, off);

            l_run[r] = l_run[r] * corr + lsum;

            #pragma unroll
            for (int d = 0; d < 8; d++) o_acc[r][d] *= corr;

            #pragma unroll
            for (int c = 0; c < 4; c++)
                sP[(ty * 4 + r) * P_STRIDE + c * 16 + tx] = acc[r][c];
        }
        __syncthreads();

        // ---- O += P @ V : rows ty*4+r, cols tx*8..+7 ----
        const float4* sV4 = reinterpret_cast<const float4*>(sV);
        #pragma unroll 4
        for (int j = 0; j < BN; j++) {
            float4 v0 = sV4[j * 33 + tx * 2];
            float4 v1 = sV4[j * 33 + tx * 2 + 1];
            #pragma unroll
            for (int r = 0; r < 4; r++) {
                float p = sP[(ty * 4 + r) * P_STRIDE + j];
                o_acc[r][0] += p * v0.x;
                o_acc[r][1] += p * v0.y;
                o_acc[r][2] += p * v0.z;
                o_acc[r][3] += p * v0.w;
                o_acc[r][4] += p * v1.x;
                o_acc[r][5] += p * v1.y;
                o_acc[r][6] += p * v1.z;
                o_acc[r][7] += p * v1.w;
            }
        }
    }

    // ---- epilogue: normalize and store ----
    #pragma unroll
    for (int r = 0; r < 4; r++) {
        float inv = 1.0f / l_run[r];
        float4 a, b;
        a.x = o_acc[r][0] * inv; a.y = o_acc[r][1] * inv;
        a.z = o_acc[r][2] * inv; a.w = o_acc[r][3] * inv;
        b.x = o_acc[r][4] * inv; b.y = o_acc[r][5] * inv;
        b.z = o_acc[r][6] * inv; b.w = o_acc[r][7] * inv;
        float4* orow = reinterpret_cast<float4*>(Ob + (size_t)(q0 + ty * 4 + r) * DH);
        orow[tx * 2]     = a;
        orow[tx * 2 + 1] = b;
    }
}

extern "C" void kernel_launch(void* const* d_in, const int* in_sizes, int n_in,
                              void* d_out, int out_size)
{
    const float* Q = (const float*)d_in[0];
    const float* K = (const float*)d_in[1];
    const float* V = (const float*)d_in[2];
    // d_in[3] = mask : ignored (causal mask applied analytically)
    float* O = (float*)d_out;

    const int smem_bytes = (3 * BM * KV_STRIDE + BM * P_STRIDE) * (int)sizeof(float); // 118784
    cudaFuncSetAttribute(fa_fp32_kernel, cudaFuncAttributeMaxDynamicSharedMemorySize, smem_bytes);

    dim3 grid(S_SEQ / BM, 2 * 16);   // (32 q-tiles, B*H=32)
    fa_fp32_kernel<<<grid, NTHREADS, smem_bytes>>>(Q, K, V, O);
}